// round 13
// baseline (speedup 1.0000x reference)
#include <cuda_runtime.h>
#include <cuda_fp16.h>
#include <cstdint>
#include <cstddef>

#define MAXN 100000
#define MAXE 1600000
#define HD   128

// ---------------- static device scratch ----------------
__device__ uint32_t g_h  [(size_t)MAXN * 64];   // GEMM out, packed fp16x2 (gathered)
__device__ uint32_t g_y  [(size_t)MAXN * 64];   // aggregate out, packed fp16x2
__device__ float    g_dinv[MAXN];
__device__ int      g_cnt [MAXN];
__device__ int      g_rowptr[MAXN];
__device__ int      g_cursor[MAXN];
__device__ int      g_csr [MAXE];
__device__ int      g_bsum[256];
__device__ uint32_t g_whi1[8192], g_wlo1[8192];
__device__ uint32_t g_whi2[8192], g_wlo2[8192];
__device__ uint32_t g_whi3[8192], g_wlo3[8192];

// ---------------- helpers ----------------
__device__ __forceinline__ void hsplit(float f, __half& h, __half& l) {
    h = __float2half_rn(f);
    l = __float2half_rn(f - __half2float(h));
}
__device__ __forceinline__ uint32_t hpack(__half a, __half b) {
    return ((uint32_t)__half_as_ushort(b) << 16) | (uint32_t)__half_as_ushort(a);
}
__device__ __forceinline__ void mma16816(float* d, const uint32_t* a, const uint32_t* b) {
    asm volatile("mma.sync.aligned.m16n8k16.row.col.f32.f16.f16.f32 "
        "{%0,%1,%2,%3}, {%4,%5,%6,%7}, {%8,%9}, {%0,%1,%2,%3};"
        : "+f"(d[0]), "+f"(d[1]), "+f"(d[2]), "+f"(d[3])
        : "r"(a[0]), "r"(a[1]), "r"(a[2]), "r"(a[3]), "r"(b[0]), "r"(b[1]));
}
__device__ __forceinline__ void wsplit_one(const float* __restrict__ W,
                                           uint32_t* whi, uint32_t* wlo, int i) {
    int nn = i >> 6;
    int k2 = i & 63;
    float f0 = __ldg(W + (size_t)(2 * k2)     * 128 + nn);
    float f1 = __ldg(W + (size_t)(2 * k2 + 1) * 128 + nn);
    __half h0, l0, h1, l1;
    hsplit(f0, h0, l0);
    hsplit(f1, h1, l1);
    whi[i] = hpack(h0, h1);
    wlo[i] = hpack(l0, l1);
}
__device__ __forceinline__ void addv(float4& a, uint2 v) {
    float2 p0 = __half22float2(*(__half2*)&v.x);
    float2 p1 = __half22float2(*(__half2*)&v.y);
    a.x += p0.x; a.y += p0.y; a.z += p1.x; a.w += p1.y;
}

// ---------------- init / CSR build ----------------
__global__ void k_init(const float* __restrict__ W1, uint32_t* whi, uint32_t* wlo,
                       int* cnt, int n) {
    int i = blockIdx.x * blockDim.x + threadIdx.x;
    if (i < n) cnt[i] = 0;
    if (i < 8192) wsplit_one(W1, whi, wlo, i);
}
__global__ void k_count(const int* __restrict__ dst, int* cnt, int e) {
    int i = blockIdx.x * blockDim.x + threadIdx.x;
    if (i < e) atomicAdd(&cnt[dst[i]], 1);
}
__global__ void k_dinv(const int* __restrict__ cnt, float* dinv, int n) {
    int i = blockIdx.x * blockDim.x + threadIdx.x;
    if (i < n) dinv[i] = rsqrtf((float)(cnt[i] + 1));
}
__global__ void k_wsplit2(const float* __restrict__ W2, uint32_t* whi2, uint32_t* wlo2,
                          const float* __restrict__ W3, uint32_t* whi3, uint32_t* wlo3) {
    int i = blockIdx.x * blockDim.x + threadIdx.x;
    if (i < 8192) {
        wsplit_one(W2, whi2, wlo2, i);
        wsplit_one(W3, whi3, wlo3, i);
    }
}
__global__ void k_scan_block(const int* __restrict__ in, int* out, int* bsum, int n) {
    __shared__ int s[512];
    int i = blockIdx.x * 512 + threadIdx.x;
    int v = (i < n) ? in[i] : 0;
    s[threadIdx.x] = v;
    __syncthreads();
    #pragma unroll
    for (int o = 1; o < 512; o <<= 1) {
        int t = (threadIdx.x >= o) ? s[threadIdx.x - o] : 0;
        __syncthreads();
        s[threadIdx.x] += t;
        __syncthreads();
    }
    if (i < n) out[i] = s[threadIdx.x] - v;
    if (threadIdx.x == 511) bsum[blockIdx.x] = s[511];
}
__global__ void k_scan_sums(int* bsum, int nb) {
    __shared__ int s[256];
    int v = (threadIdx.x < nb) ? bsum[threadIdx.x] : 0;
    s[threadIdx.x] = v;
    __syncthreads();
    #pragma unroll
    for (int o = 1; o < 256; o <<= 1) {
        int t = (threadIdx.x >= o) ? s[threadIdx.x - o] : 0;
        __syncthreads();
        s[threadIdx.x] += t;
        __syncthreads();
    }
    if (threadIdx.x < nb) bsum[threadIdx.x] = s[threadIdx.x] - v;
}
__global__ void k_scan_add(int* out, int* cursor, const int* __restrict__ bsum, int n) {
    int i = blockIdx.x * 512 + threadIdx.x;
    if (i < n) {
        int v = out[i] + bsum[blockIdx.x];
        out[i] = v;
        cursor[i] = v;
    }
}
__global__ void k_fill(const int* __restrict__ src, const int* __restrict__ dst,
                       int* cursor, int* csr, int e) {
    int i = blockIdx.x * blockDim.x + threadIdx.x;
    if (i < e) {
        int p = atomicAdd(&cursor[dst[i]], 1);
        csr[p] = src[i];
    }
}

// ---------------- GEMM core: 64-row tile, 3 CTAs/SM ----------------
#define ROWSTR 36
#define ABUF   (64 * ROWSTR)           // 2304 u32
#define BBUF   (128 * ROWSTR)          // 4608 u32
#define GEMM_SMEM ((ABUF + 2 * BBUF) * 4)   // 46080

struct GemmCore {
    template <typename AFill>
    static __device__ __forceinline__
    void run(AFill afill, const uint32_t* __restrict__ Bhi, const uint32_t* __restrict__ Blo,
             const float* __restrict__ dinv, uint32_t* __restrict__ C, int n,
             uint32_t* sm) {
        uint32_t* As    = sm;
        uint32_t* Bs_hi = sm + ABUF;
        uint32_t* Bs_lo = sm + ABUF + BBUF;

        const int tid  = threadIdx.x;
        const int wid  = tid >> 5;
        const int lane = tid & 31;
        const int qg   = lane >> 2;
        const int qt   = lane & 3;
        const int wm   = wid & 3;          // rows wm*16..+15
        const int wn   = wid >> 2;         // cols wn*64..+63
        const int r0   = blockIdx.x * 64;

        float acc[8][4];
        #pragma unroll
        for (int b = 0; b < 8; b++)
            #pragma unroll
            for (int c = 0; c < 4; c++) acc[b][c] = 0.f;

        #pragma unroll
        for (int ch = 0; ch < 2; ch++) {
            __syncthreads();
            afill(As, ch, r0, tid, n);
            #pragma unroll
            for (int it = 0; it < 16; it++) {
                int i  = tid + it * 256;
                int nn = i >> 5;
                int k2 = i & 31;
                Bs_hi[nn * ROWSTR + k2] = __ldg(Bhi + nn * 64 + ch * 32 + k2);
                Bs_lo[nn * ROWSTR + k2] = __ldg(Blo + nn * 64 + ch * 32 + k2);
            }
            __syncthreads();

            #pragma unroll
            for (int ks = 0; ks < 4; ks++) {
                uint32_t ah[4];
                int rb = wm * 16;
                int p0 = (rb + qg)     * ROWSTR + ks * 8 + qt;
                int p8 = (rb + qg + 8) * ROWSTR + ks * 8 + qt;
                ah[0] = As[p0]; ah[1] = As[p8];
                ah[2] = As[p0 + 4]; ah[3] = As[p8 + 4];
                #pragma unroll
                for (int nt = 0; nt < 8; nt++) {
                    int nb = (wn * 64 + nt * 8 + qg) * ROWSTR + ks * 8 + qt;
                    uint32_t bh[2] = {Bs_hi[nb], Bs_hi[nb + 4]};
                    uint32_t bl[2] = {Bs_lo[nb], Bs_lo[nb + 4]};
                    mma16816(acc[nt], ah, bh);
                    mma16816(acc[nt], ah, bl);
                }
            }
        }

        int row0 = r0 + wm * 16 + qg;
        int row1 = row0 + 8;
        float dv0 = (row0 < n) ? __ldg(dinv + row0) : 0.f;
        float dv1 = (row1 < n) ? __ldg(dinv + row1) : 0.f;
        #pragma unroll
        for (int nt = 0; nt < 8; nt++) {
            int c2 = wn * 32 + nt * 4 + qt;
            if (row0 < n)
                C[(size_t)row0 * 64 + c2] = hpack(__float2half_rn(acc[nt][0] * dv0),
                                                  __float2half_rn(acc[nt][1] * dv0));
            if (row1 < n)
                C[(size_t)row1 * 64 + c2] = hpack(__float2half_rn(acc[nt][2] * dv1),
                                                  __float2half_rn(acc[nt][3] * dv1));
        }
    }
};

// GEMM1: A from fp32 x (convert in-kernel). Per chunk: 64 rows x 16 float4 = 1024.
__global__ void __launch_bounds__(256, 3)
k_gemm_f32a(const float* __restrict__ A, const uint32_t* __restrict__ Bhi,
            const uint32_t* __restrict__ Blo, const float* __restrict__ dinv,
            uint32_t* __restrict__ C, int n) {
    extern __shared__ uint32_t sm[];
    auto afill = [A](uint32_t* As, int ch, int r0, int tid, int n) {
        #pragma unroll
        for (int it = 0; it < 4; it++) {
            int f   = tid + it * 256;
            int row = f >> 4;
            int q   = f & 15;
            int gr  = r0 + row;
            float4 v = make_float4(0.f, 0.f, 0.f, 0.f);
            if (gr < n) v = *(const float4*)(A + (size_t)gr * 128 + ch * 64 + q * 4);
            int p = row * ROWSTR + q * 2;
            As[p]     = hpack(__float2half_rn(v.x), __float2half_rn(v.y));
            As[p + 1] = hpack(__float2half_rn(v.z), __float2half_rn(v.w));
        }
    };
    GemmCore::run(afill, Bhi, Blo, dinv, C, n, sm);
}

// GEMM2/3: A from packed fp16 y (pure copy). Per chunk: 64 rows x 16 uint2 = 1024.
__global__ void __launch_bounds__(256, 3)
k_gemm_h16a(const uint32_t* __restrict__ A, const uint32_t* __restrict__ Bhi,
            const uint32_t* __restrict__ Blo, const float* __restrict__ dinv,
            uint32_t* __restrict__ C, int n) {
    extern __shared__ uint32_t sm[];
    auto afill = [A](uint32_t* As, int ch, int r0, int tid, int n) {
        #pragma unroll
        for (int it = 0; it < 4; it++) {
            int i   = tid + it * 256;
            int row = i >> 4;
            int k4  = (i & 15) * 2;
            int gr  = r0 + row;
            uint2 v = make_uint2(0u, 0u);
            if (gr < n) v = *(const uint2*)(A + (size_t)gr * 64 + ch * 32 + k4);
            *(uint2*)(As + row * ROWSTR + k4) = v;
        }
    };
    GemmCore::run(afill, Bhi, Blo, dinv, C, n, sm);
}

// ---------------- aggregate (fp16 gather) + bias/relu/BN -> y packed fp16 ----------------
__global__ void k_aggregate(const uint32_t* __restrict__ hs,
                            const int* __restrict__ rowptr, const int* __restrict__ cnt,
                            const float* __restrict__ dinv,
                            const float* __restrict__ b,  const float* __restrict__ g,
                            const float* __restrict__ be, const float* __restrict__ rm,
                            const float* __restrict__ rv, const int* __restrict__ csr,
                            uint32_t* __restrict__ y, int n) {
    int warp = (blockIdx.x * blockDim.x + threadIdx.x) >> 5;
    int lane = threadIdx.x & 31;
    int nw   = (gridDim.x * blockDim.x) >> 5;
    int j    = lane * 4;

    float4 bb = __ldg((const float4*)(b  + j));
    float4 gg = __ldg((const float4*)(g  + j));
    float4 rr = __ldg((const float4*)(rv + j));
    float4 mm = __ldg((const float4*)(rm + j));
    float4 ee = __ldg((const float4*)(be + j));
    float sc0 = gg.x * rsqrtf(rr.x + 1e-5f), sh0 = ee.x - mm.x * sc0;
    float sc1 = gg.y * rsqrtf(rr.y + 1e-5f), sh1 = ee.y - mm.y * sc1;
    float sc2 = gg.z * rsqrtf(rr.z + 1e-5f), sh2 = ee.z - mm.z * sc2;
    float sc3 = gg.w * rsqrtf(rr.w + 1e-5f), sh3 = ee.w - mm.w * sc3;

    for (int d = warp; d < n; d += nw) {
        float4 a = make_float4(0.f, 0.f, 0.f, 0.f);
        uint2 vs = __ldg((const uint2*)(hs + (size_t)d * 64) + lane);   // self loop
        int beg = __ldg(rowptr + d);
        int c   = __ldg(cnt + d);
        int k = 0;
        for (; k + 4 <= c; k += 4) {
            int s0 = __ldg(csr + beg + k);
            int s1 = __ldg(csr + beg + k + 1);
            int s2 = __ldg(csr + beg + k + 2);
            int s3 = __ldg(csr + beg + k + 3);
            uint2 v0 = __ldg((const uint2*)(hs + (size_t)s0 * 64) + lane);
            uint2 v1 = __ldg((const uint2*)(hs + (size_t)s1 * 64) + lane);
            uint2 v2 = __ldg((const uint2*)(hs + (size_t)s2 * 64) + lane);
            uint2 v3 = __ldg((const uint2*)(hs + (size_t)s3 * 64) + lane);
            addv(a, v0); addv(a, v1); addv(a, v2); addv(a, v3);
        }
        for (; k < c; k++) {
            uint2 v = __ldg((const uint2*)(hs + (size_t)__ldg(csr + beg + k) * 64) + lane);
            addv(a, v);
        }
        addv(a, vs);

        float w = __ldg(dinv + d);
        float t0 = fmaxf(a.x * w + bb.x, 0.f);
        float t1 = fmaxf(a.y * w + bb.y, 0.f);
        float t2 = fmaxf(a.z * w + bb.z, 0.f);
        float t3 = fmaxf(a.w * w + bb.w, 0.f);
        uint2 o;
        o.x = hpack(__float2half_rn(t0 * sc0 + sh0), __float2half_rn(t1 * sc1 + sh1));
        o.y = hpack(__float2half_rn(t2 * sc2 + sh2), __float2half_rn(t3 * sc3 + sh3));
        *((uint2*)(y + (size_t)d * 64) + lane) = o;
    }
}

// ---------------- fused aggregate -> classifier (layer 3) ----------------
__global__ void k_agg_cls(const uint32_t* __restrict__ hin,
                          const int* __restrict__ rowptr, const int* __restrict__ cnt,
                          const float* __restrict__ dinv, const int* __restrict__ csr,
                          const float* __restrict__ bias, const float* __restrict__ gam,
                          const float* __restrict__ bet, const float* __restrict__ rmean,
                          const float* __restrict__ rvar,
                          const float* __restrict__ Wc, const float* __restrict__ bc,
                          float* __restrict__ out, int n) {
    int warp = (blockIdx.x * blockDim.x + threadIdx.x) >> 5;
    int lane = threadIdx.x & 31;
    int nw   = (gridDim.x * blockDim.x) >> 5;
    int j    = lane * 4;

    float4 bb = __ldg((const float4*)(bias  + j));
    float4 gg = __ldg((const float4*)(gam   + j));
    float4 rr = __ldg((const float4*)(rvar  + j));
    float4 mm = __ldg((const float4*)(rmean + j));
    float4 ee = __ldg((const float4*)(bet   + j));
    float sc0 = gg.x * rsqrtf(rr.x + 1e-5f), sh0 = ee.x - mm.x * sc0;
    float sc1 = gg.y * rsqrtf(rr.y + 1e-5f), sh1 = ee.y - mm.y * sc1;
    float sc2 = gg.z * rsqrtf(rr.z + 1e-5f), sh2 = ee.z - mm.z * sc2;
    float sc3 = gg.w * rsqrtf(rr.w + 1e-5f), sh3 = ee.w - mm.w * sc3;
    float w00 = __ldg(Wc + (j + 0) * 2), w01 = __ldg(Wc + (j + 0) * 2 + 1);
    float w10 = __ldg(Wc + (j + 1) * 2), w11 = __ldg(Wc + (j + 1) * 2 + 1);
    float w20 = __ldg(Wc + (j + 2) * 2), w21 = __ldg(Wc + (j + 2) * 2 + 1);
    float w30 = __ldg(Wc + (j + 3) * 2), w31 = __ldg(Wc + (j + 3) * 2 + 1);
    float bc0 = __ldg(bc), bc1 = __ldg(bc + 1);

    for (int d = warp; d < n; d += nw) {
        float4 a = make_float4(0.f, 0.f, 0.f, 0.f);
        uint2 vs = __ldg((const uint2*)(hin + (size_t)d * 64) + lane);
        int beg = __ldg(rowptr + d);
        int c   = __ldg(cnt + d);
        int k = 0;
        for (; k + 4 <= c; k += 4) {
            int s0 = __ldg(csr + beg + k);
            int s1 = __ldg(csr + beg + k + 1);
            int s2 = __ldg(csr + beg + k + 2);
            int s3 = __ldg(csr + beg + k + 3);
            uint2 v0 = __ldg((const uint2*)(hin + (size_t)s0 * 64) + lane);
            uint2 v1 = __ldg((const uint2*)(hin + (size_t)s1 * 64) + lane);
            uint2 v2 = __ldg((const uint2*)(hin + (size_t)s2 * 64) + lane);
            uint2 v3 = __ldg((const uint2*)(hin + (size_t)s3 * 64) + lane);
            addv(a, v0); addv(a, v1); addv(a, v2); addv(a, v3);
        }
        for (; k < c; k++) {
            uint2 v = __ldg((const uint2*)(hin + (size_t)__ldg(csr + beg + k) * 64) + lane);
            addv(a, v);
        }
        addv(a, vs);

        float dd = __ldg(dinv + d);
        float t0 = fmaxf(a.x * dd + bb.x, 0.f);
        float t1 = fmaxf(a.y * dd + bb.y, 0.f);
        float t2 = fmaxf(a.z * dd + bb.z, 0.f);
        float t3 = fmaxf(a.w * dd + bb.w, 0.f);
        float o0 = t0 * sc0 + sh0, o1 = t1 * sc1 + sh1;
        float o2 = t2 * sc2 + sh2, o3 = t3 * sc3 + sh3;
        float a0 = o0 * w00 + o1 * w10 + o2 * w20 + o3 * w30;
        float a1 = o0 * w01 + o1 * w11 + o2 * w21 + o3 * w31;
        #pragma unroll
        for (int o = 16; o > 0; o >>= 1) {
            a0 += __shfl_xor_sync(0xFFFFFFFFu, a0, o);
            a1 += __shfl_xor_sync(0xFFFFFFFFu, a1, o);
        }
        if (lane == 0) {
            out[(size_t)d * 2]     = a0 + bc0;
            out[(size_t)d * 2 + 1] = a1 + bc1;
        }
    }
}

// ---------------- launcher ----------------
extern "C" void kernel_launch(void* const* d_in, const int* in_sizes, int n_in,
                              void* d_out, int out_size) {
    const float* x   = (const float*)d_in[0];
    const int*   ei  = (const int*)  d_in[1];
    const float* W1  = (const float*)d_in[2];
    const float* b1  = (const float*)d_in[3];
    const float* W2  = (const float*)d_in[4];
    const float* b2  = (const float*)d_in[5];
    const float* W3  = (const float*)d_in[6];
    const float* b3  = (const float*)d_in[7];
    const float* g1  = (const float*)d_in[8];
    const float* be1 = (const float*)d_in[9];
    const float* rm1 = (const float*)d_in[10];
    const float* rv1 = (const float*)d_in[11];
    const float* g2  = (const float*)d_in[12];
    const float* be2 = (const float*)d_in[13];
    const float* rm2 = (const float*)d_in[14];
    const float* rv2 = (const float*)d_in[15];
    const float* g3  = (const float*)d_in[16];
    const float* be3 = (const float*)d_in[17];
    const float* rm3 = (const float*)d_in[18];
    const float* rv3 = (const float*)d_in[19];
    const float* Wc  = (const float*)d_in[20];
    const float* bc  = (const float*)d_in[21];
    float* out = (float*)d_out;

    int n = in_sizes[0] / HD;
    int e = in_sizes[1] / 2;
    const int* src = ei;
    const int* dst = ei + e;

    float *pdinv;
    uint32_t *ph, *py;
    int *pcnt, *prow, *pcur, *pcsr, *pbsum;
    uint32_t *pwhi1, *pwlo1, *pwhi2, *pwlo2, *pwhi3, *pwlo3;
    cudaGetSymbolAddress((void**)&ph,    g_h);
    cudaGetSymbolAddress((void**)&py,    g_y);
    cudaGetSymbolAddress((void**)&pdinv, g_dinv);
    cudaGetSymbolAddress((void**)&pcnt,  g_cnt);
    cudaGetSymbolAddress((void**)&prow,  g_rowptr);
    cudaGetSymbolAddress((void**)&pcur,  g_cursor);
    cudaGetSymbolAddress((void**)&pcsr,  g_csr);
    cudaGetSymbolAddress((void**)&pbsum, g_bsum);
    cudaGetSymbolAddress((void**)&pwhi1, g_whi1);
    cudaGetSymbolAddress((void**)&pwlo1, g_wlo1);
    cudaGetSymbolAddress((void**)&pwhi2, g_whi2);
    cudaGetSymbolAddress((void**)&pwlo2, g_wlo2);
    cudaGetSymbolAddress((void**)&pwhi3, g_whi3);
    cudaGetSymbolAddress((void**)&pwlo3, g_wlo3);

    cudaFuncSetAttribute(k_gemm_f32a, cudaFuncAttributeMaxDynamicSharedMemorySize, GEMM_SMEM);
    cudaFuncSetAttribute(k_gemm_h16a, cudaFuncAttributeMaxDynamicSharedMemorySize, GEMM_SMEM);

    const int T = 256;
    int bn_n  = (n + T - 1) / T;
    int bn_e  = (e + T - 1) / T;
    int bn_gm = (n + 63) / 64;
    int nb_sc = (n + 511) / 512;
    int bn_ag = 4096;

    // init + degree (GEMM1 at 4th launch = profiled slot)
    k_init  <<<bn_n, T>>>(W1, pwhi1, pwlo1, pcnt, n);
    k_count <<<bn_e, T>>>(dst, pcnt, e);
    k_dinv  <<<bn_n, T>>>(pcnt, pdinv, n);
    k_gemm_f32a<<<bn_gm, T, GEMM_SMEM>>>(x, pwhi1, pwlo1, pdinv, ph, n);

    // CSR build + W2/W3 splits
    k_wsplit2   <<<32, T>>>(W2, pwhi2, pwlo2, W3, pwhi3, pwlo3);
    k_scan_block<<<nb_sc, 512>>>(pcnt, prow, pbsum, n);
    k_scan_sums <<<1, 256>>>(pbsum, nb_sc);
    k_scan_add  <<<nb_sc, 512>>>(prow, pcur, pbsum, n);
    k_fill      <<<bn_e, T>>>(src, dst, pcur, pcsr, e);

    // layer 1 aggregate -> layer 2
    k_aggregate<<<bn_ag, T>>>(ph, prow, pcnt, pdinv, b1, g1, be1, rm1, rv1, pcsr, py, n);
    k_gemm_h16a<<<bn_gm, T, GEMM_SMEM>>>(py, pwhi2, pwlo2, pdinv, ph, n);
    // layer 2 aggregate -> layer 3
    k_aggregate<<<bn_ag, T>>>(ph, prow, pcnt, pdinv, b2, g2, be2, rm2, rv2, pcsr, py, n);
    k_gemm_h16a<<<bn_gm, T, GEMM_SMEM>>>(py, pwhi3, pwlo3, pdinv, ph, n);
    // layer 3 aggregate fused with classifier
    k_agg_cls  <<<bn_ag, T>>>(ph, prow, pcnt, pdinv, pcsr,
                              b3, g3, be3, rm3, rv3, Wc, bc, out, n);
}

// round 15
// speedup vs baseline: 1.0837x; 1.0837x over previous
#include <cuda_runtime.h>
#include <cuda_fp16.h>
#include <cstdint>
#include <cstddef>

#define MAXN 100000
#define MAXE 1600000
#define HD   128

// ---------------- static device scratch ----------------
__device__ uint32_t g_h  [(size_t)MAXN * 64];   // GEMM out, packed fp16x2 (gathered)
__device__ uint32_t g_y  [(size_t)MAXN * 64];   // aggregate out, packed fp16x2
__device__ float    g_dinv[MAXN];
__device__ int      g_cnt [MAXN];
__device__ int      g_rowptr[MAXN];
__device__ int      g_cursor[MAXN];
__device__ int      g_csr [MAXE];
__device__ int      g_bsum[256];
__device__ uint32_t g_whi1[8192], g_wlo1[8192];
__device__ uint32_t g_whi2[8192], g_wlo2[8192];
__device__ uint32_t g_whi3[8192], g_wlo3[8192];

// ---------------- helpers ----------------
__device__ __forceinline__ void hsplit(float f, __half& h, __half& l) {
    h = __float2half_rn(f);
    l = __float2half_rn(f - __half2float(h));
}
__device__ __forceinline__ uint32_t hpack(__half a, __half b) {
    return ((uint32_t)__half_as_ushort(b) << 16) | (uint32_t)__half_as_ushort(a);
}
__device__ __forceinline__ void mma16816(float* d, const uint32_t* a, const uint32_t* b) {
    asm volatile("mma.sync.aligned.m16n8k16.row.col.f32.f16.f16.f32 "
        "{%0,%1,%2,%3}, {%4,%5,%6,%7}, {%8,%9}, {%0,%1,%2,%3};"
        : "+f"(d[0]), "+f"(d[1]), "+f"(d[2]), "+f"(d[3])
        : "r"(a[0]), "r"(a[1]), "r"(a[2]), "r"(a[3]), "r"(b[0]), "r"(b[1]));
}
__device__ __forceinline__ void wsplit_one(const float* __restrict__ W,
                                           uint32_t* whi, uint32_t* wlo, int i) {
    int nn = i >> 6;
    int k2 = i & 63;
    float f0 = __ldg(W + (size_t)(2 * k2)     * 128 + nn);
    float f1 = __ldg(W + (size_t)(2 * k2 + 1) * 128 + nn);
    __half h0, l0, h1, l1;
    hsplit(f0, h0, l0);
    hsplit(f1, h1, l1);
    whi[i] = hpack(h0, h1);
    wlo[i] = hpack(l0, l1);
}
__device__ __forceinline__ void addv(float4& a, uint2 v) {
    float2 p0 = __half22float2(*(__half2*)&v.x);
    float2 p1 = __half22float2(*(__half2*)&v.y);
    a.x += p0.x; a.y += p0.y; a.z += p1.x; a.w += p1.y;
}

// ---------------- init / CSR build ----------------
__global__ void k_init(const float* __restrict__ W1, uint32_t* whi, uint32_t* wlo,
                       int* cnt, int n) {
    int i = blockIdx.x * blockDim.x + threadIdx.x;
    if (i < n) cnt[i] = 0;
    if (i < 8192) wsplit_one(W1, whi, wlo, i);
}
__global__ void k_count(const int* __restrict__ dst, int* cnt, int e) {
    int i = blockIdx.x * blockDim.x + threadIdx.x;
    if (i < e) atomicAdd(&cnt[dst[i]], 1);
}
__global__ void k_dinv(const int* __restrict__ cnt, float* dinv, int n) {
    int i = blockIdx.x * blockDim.x + threadIdx.x;
    if (i < n) dinv[i] = rsqrtf((float)(cnt[i] + 1));
}
__global__ void k_wsplit2(const float* __restrict__ W2, uint32_t* whi2, uint32_t* wlo2,
                          const float* __restrict__ W3, uint32_t* whi3, uint32_t* wlo3) {
    int i = blockIdx.x * blockDim.x + threadIdx.x;
    if (i < 8192) {
        wsplit_one(W2, whi2, wlo2, i);
        wsplit_one(W3, whi3, wlo3, i);
    }
}
__global__ void k_scan_block(const int* __restrict__ in, int* out, int* bsum, int n) {
    __shared__ int s[512];
    int i = blockIdx.x * 512 + threadIdx.x;
    int v = (i < n) ? in[i] : 0;
    s[threadIdx.x] = v;
    __syncthreads();
    #pragma unroll
    for (int o = 1; o < 512; o <<= 1) {
        int t = (threadIdx.x >= o) ? s[threadIdx.x - o] : 0;
        __syncthreads();
        s[threadIdx.x] += t;
        __syncthreads();
    }
    if (i < n) out[i] = s[threadIdx.x] - v;
    if (threadIdx.x == 511) bsum[blockIdx.x] = s[511];
}
__global__ void k_scan_sums(int* bsum, int nb) {
    __shared__ int s[256];
    int v = (threadIdx.x < nb) ? bsum[threadIdx.x] : 0;
    s[threadIdx.x] = v;
    __syncthreads();
    #pragma unroll
    for (int o = 1; o < 256; o <<= 1) {
        int t = (threadIdx.x >= o) ? s[threadIdx.x - o] : 0;
        __syncthreads();
        s[threadIdx.x] += t;
        __syncthreads();
    }
    if (threadIdx.x < nb) bsum[threadIdx.x] = s[threadIdx.x] - v;
}
__global__ void k_scan_add(int* out, int* cursor, const int* __restrict__ bsum, int n) {
    int i = blockIdx.x * 512 + threadIdx.x;
    if (i < n) {
        int v = out[i] + bsum[blockIdx.x];
        out[i] = v;
        cursor[i] = v;
    }
}
__global__ void k_fill(const int* __restrict__ src, const int* __restrict__ dst,
                       int* cursor, int* csr, int e) {
    int i = blockIdx.x * blockDim.x + threadIdx.x;
    if (i < e) {
        int p = atomicAdd(&cursor[dst[i]], 1);
        csr[p] = src[i];
    }
}

// ---------------- GEMM core: 128-row tile, single-sync (all LDG up front) ----------
#define AROW   68
#define ABUF   (128 * AROW)            // 8704 u32 (full K)
#define BROW   36
#define BBUF   (128 * BROW)            // 4608 u32 (one chunk, one of hi/lo)
#define GEMM_SMEM ((ABUF + 4 * BBUF) * 4)   // 108544

struct GemmCore {
    template <typename AFill>
    static __device__ __forceinline__
    void run(AFill afill, const uint32_t* __restrict__ Bhi, const uint32_t* __restrict__ Blo,
             const float* __restrict__ dinv, uint32_t* __restrict__ C, int n,
             uint32_t* sm) {
        uint32_t* As = sm;
        uint32_t* Bs = sm + ABUF;      // [ch*2 + (0=hi,1=lo)] * BBUF

        const int tid  = threadIdx.x;
        const int wid  = tid >> 5;
        const int lane = tid & 31;
        const int qg   = lane >> 2;
        const int qt   = lane & 3;
        const int wm   = wid & 3;
        const int wn   = wid >> 2;
        const int r0   = blockIdx.x * 128;

        // ---- ALL global loads up front, then one sync ----
        afill(As, r0, tid, n);
        #pragma unroll
        for (int ch = 0; ch < 2; ch++) {
            uint32_t* bh = Bs + (ch * 2)     * BBUF;
            uint32_t* bl = Bs + (ch * 2 + 1) * BBUF;
            #pragma unroll
            for (int it = 0; it < 16; it++) {
                int i  = tid + it * 256;
                int nn = i >> 5;
                int k2 = i & 31;
                bh[nn * BROW + k2] = __ldg(Bhi + nn * 64 + ch * 32 + k2);
                bl[nn * BROW + k2] = __ldg(Blo + nn * 64 + ch * 32 + k2);
            }
        }
        __syncthreads();

        float acc[2][8][4];
        #pragma unroll
        for (int a = 0; a < 2; a++)
            #pragma unroll
            for (int b = 0; b < 8; b++)
                #pragma unroll
                for (int c = 0; c < 4; c++) acc[a][b][c] = 0.f;

        #pragma unroll
        for (int ch = 0; ch < 2; ch++) {
            uint32_t* bhp = Bs + (ch * 2)     * BBUF;
            uint32_t* blp = Bs + (ch * 2 + 1) * BBUF;
            #pragma unroll
            for (int ks = 0; ks < 4; ks++) {
                uint32_t ah[2][4];
                #pragma unroll
                for (int mt = 0; mt < 2; mt++) {
                    int rb = wm * 32 + mt * 16;
                    int p0 = (rb + qg)     * AROW + ch * 32 + ks * 8 + qt;
                    int p8 = (rb + qg + 8) * AROW + ch * 32 + ks * 8 + qt;
                    ah[mt][0] = As[p0]; ah[mt][1] = As[p8];
                    ah[mt][2] = As[p0 + 4]; ah[mt][3] = As[p8 + 4];
                }
                #pragma unroll
                for (int nt = 0; nt < 8; nt++) {
                    int nb = (wn * 64 + nt * 8 + qg) * BROW + ks * 8 + qt;
                    uint32_t bh[2] = {bhp[nb], bhp[nb + 4]};
                    uint32_t bl[2] = {blp[nb], blp[nb + 4]};
                    #pragma unroll
                    for (int mt = 0; mt < 2; mt++) {
                        mma16816(acc[mt][nt], ah[mt], bh);
                        mma16816(acc[mt][nt], ah[mt], bl);
                    }
                }
            }
        }

        #pragma unroll
        for (int mt = 0; mt < 2; mt++) {
            int row0 = r0 + wm * 32 + mt * 16 + qg;
            int row1 = row0 + 8;
            float dv0 = (row0 < n) ? __ldg(dinv + row0) : 0.f;
            float dv1 = (row1 < n) ? __ldg(dinv + row1) : 0.f;
            #pragma unroll
            for (int nt = 0; nt < 8; nt++) {
                int c2 = wn * 32 + nt * 4 + qt;
                if (row0 < n)
                    C[(size_t)row0 * 64 + c2] = hpack(__float2half_rn(acc[mt][nt][0] * dv0),
                                                      __float2half_rn(acc[mt][nt][1] * dv0));
                if (row1 < n)
                    C[(size_t)row1 * 64 + c2] = hpack(__float2half_rn(acc[mt][nt][2] * dv1),
                                                      __float2half_rn(acc[mt][nt][3] * dv1));
            }
        }
    }
};

// GEMM1: A from fp32 x (convert in-kernel), full-K fill (4096 float4 per CTA)
__global__ void __launch_bounds__(256, 2)
k_gemm_f32a(const float* __restrict__ A, const uint32_t* __restrict__ Bhi,
            const uint32_t* __restrict__ Blo, const float* __restrict__ dinv,
            uint32_t* __restrict__ C, int n) {
    extern __shared__ uint32_t sm[];
    auto afill = [A](uint32_t* As, int r0, int tid, int n) {
        #pragma unroll
        for (int it = 0; it < 16; it++) {
            int i   = tid + it * 256;
            int row = i >> 5;                 // 32 float4 per row
            int q   = i & 31;
            int gr  = r0 + row;
            float4 v = make_float4(0.f, 0.f, 0.f, 0.f);
            if (gr < n) v = *(const float4*)(A + (size_t)gr * 128 + q * 4);
            int p = row * AROW + q * 2;
            As[p]     = hpack(__float2half_rn(v.x), __float2half_rn(v.y));
            As[p + 1] = hpack(__float2half_rn(v.z), __float2half_rn(v.w));
        }
    };
    GemmCore::run(afill, Bhi, Blo, dinv, C, n, sm);
}

// GEMM2/3: A from packed fp16 y, full-K copy (4096 uint2 per CTA)
__global__ void __launch_bounds__(256, 2)
k_gemm_h16a(const uint32_t* __restrict__ A, const uint32_t* __restrict__ Bhi,
            const uint32_t* __restrict__ Blo, const float* __restrict__ dinv,
            uint32_t* __restrict__ C, int n) {
    extern __shared__ uint32_t sm[];
    auto afill = [A](uint32_t* As, int r0, int tid, int n) {
        #pragma unroll
        for (int it = 0; it < 16; it++) {
            int i   = tid + it * 256;          // 4096 uint2 total
            int row = i >> 5;                  // 32 uint2 per row = 64 u32 (full K)
            int k4  = (i & 31) * 2;
            int gr  = r0 + row;
            uint2 v = make_uint2(0u, 0u);
            if (gr < n) v = *(const uint2*)(A + (size_t)gr * 64 + k4);
            *(uint2*)(As + row * AROW + k4) = v;
        }
    };
    GemmCore::run(afill, Bhi, Blo, dinv, C, n, sm);
}

// ---------------- aggregate (fp16 gather) + bias/relu/BN -> y packed fp16 ----------------
__global__ void k_aggregate(const uint32_t* __restrict__ hs,
                            const int* __restrict__ rowptr, const int* __restrict__ cnt,
                            const float* __restrict__ dinv,
                            const float* __restrict__ b,  const float* __restrict__ g,
                            const float* __restrict__ be, const float* __restrict__ rm,
                            const float* __restrict__ rv, const int* __restrict__ csr,
                            uint32_t* __restrict__ y, int n) {
    int warp = (blockIdx.x * blockDim.x + threadIdx.x) >> 5;
    int lane = threadIdx.x & 31;
    int nw   = (gridDim.x * blockDim.x) >> 5;
    int j    = lane * 4;

    float4 bb = __ldg((const float4*)(b  + j));
    float4 gg = __ldg((const float4*)(g  + j));
    float4 rr = __ldg((const float4*)(rv + j));
    float4 mm = __ldg((const float4*)(rm + j));
    float4 ee = __ldg((const float4*)(be + j));
    float sc0 = gg.x * rsqrtf(rr.x + 1e-5f), sh0 = ee.x - mm.x * sc0;
    float sc1 = gg.y * rsqrtf(rr.y + 1e-5f), sh1 = ee.y - mm.y * sc1;
    float sc2 = gg.z * rsqrtf(rr.z + 1e-5f), sh2 = ee.z - mm.z * sc2;
    float sc3 = gg.w * rsqrtf(rr.w + 1e-5f), sh3 = ee.w - mm.w * sc3;

    for (int d = warp; d < n; d += nw) {
        float4 a = make_float4(0.f, 0.f, 0.f, 0.f);
        uint2 vs = __ldg((const uint2*)(hs + (size_t)d * 64) + lane);   // self loop
        int beg = __ldg(rowptr + d);
        int c   = __ldg(cnt + d);
        int k = 0;
        for (; k + 4 <= c; k += 4) {
            int s0 = __ldg(csr + beg + k);
            int s1 = __ldg(csr + beg + k + 1);
            int s2 = __ldg(csr + beg + k + 2);
            int s3 = __ldg(csr + beg + k + 3);
            uint2 v0 = __ldg((const uint2*)(hs + (size_t)s0 * 64) + lane);
            uint2 v1 = __ldg((const uint2*)(hs + (size_t)s1 * 64) + lane);
            uint2 v2 = __ldg((const uint2*)(hs + (size_t)s2 * 64) + lane);
            uint2 v3 = __ldg((const uint2*)(hs + (size_t)s3 * 64) + lane);
            addv(a, v0); addv(a, v1); addv(a, v2); addv(a, v3);
        }
        for (; k < c; k++) {
            uint2 v = __ldg((const uint2*)(hs + (size_t)__ldg(csr + beg + k) * 64) + lane);
            addv(a, v);
        }
        addv(a, vs);

        float w = __ldg(dinv + d);
        float t0 = fmaxf(a.x * w + bb.x, 0.f);
        float t1 = fmaxf(a.y * w + bb.y, 0.f);
        float t2 = fmaxf(a.z * w + bb.z, 0.f);
        float t3 = fmaxf(a.w * w + bb.w, 0.f);
        uint2 o;
        o.x = hpack(__float2half_rn(t0 * sc0 + sh0), __float2half_rn(t1 * sc1 + sh1));
        o.y = hpack(__float2half_rn(t2 * sc2 + sh2), __float2half_rn(t3 * sc3 + sh3));
        *((uint2*)(y + (size_t)d * 64) + lane) = o;
    }
}

// ---------------- fused aggregate -> classifier (layer 3) ----------------
__global__ void k_agg_cls(const uint32_t* __restrict__ hin,
                          const int* __restrict__ rowptr, const int* __restrict__ cnt,
                          const float* __restrict__ dinv, const int* __restrict__ csr,
                          const float* __restrict__ bias, const float* __restrict__ gam,
                          const float* __restrict__ bet, const float* __restrict__ rmean,
                          const float* __restrict__ rvar,
                          const float* __restrict__ Wc, const float* __restrict__ bc,
                          float* __restrict__ out, int n) {
    int warp = (blockIdx.x * blockDim.x + threadIdx.x) >> 5;
    int lane = threadIdx.x & 31;
    int nw   = (gridDim.x * blockDim.x) >> 5;
    int j    = lane * 4;

    float4 bb = __ldg((const float4*)(bias  + j));
    float4 gg = __ldg((const float4*)(gam   + j));
    float4 rr = __ldg((const float4*)(rvar  + j));
    float4 mm = __ldg((const float4*)(rmean + j));
    float4 ee = __ldg((const float4*)(bet   + j));
    float sc0 = gg.x * rsqrtf(rr.x + 1e-5f), sh0 = ee.x - mm.x * sc0;
    float sc1 = gg.y * rsqrtf(rr.y + 1e-5f), sh1 = ee.y - mm.y * sc1;
    float sc2 = gg.z * rsqrtf(rr.z + 1e-5f), sh2 = ee.z - mm.z * sc2;
    float sc3 = gg.w * rsqrtf(rr.w + 1e-5f), sh3 = ee.w - mm.w * sc3;
    float w00 = __ldg(Wc + (j + 0) * 2), w01 = __ldg(Wc + (j + 0) * 2 + 1);
    float w10 = __ldg(Wc + (j + 1) * 2), w11 = __ldg(Wc + (j + 1) * 2 + 1);
    float w20 = __ldg(Wc + (j + 2) * 2), w21 = __ldg(Wc + (j + 2) * 2 + 1);
    float w30 = __ldg(Wc + (j + 3) * 2), w31 = __ldg(Wc + (j + 3) * 2 + 1);
    float bc0 = __ldg(bc), bc1 = __ldg(bc + 1);

    for (int d = warp; d < n; d += nw) {
        float4 a = make_float4(0.f, 0.f, 0.f, 0.f);
        uint2 vs = __ldg((const uint2*)(hin + (size_t)d * 64) + lane);
        int beg = __ldg(rowptr + d);
        int c   = __ldg(cnt + d);
        int k = 0;
        for (; k + 4 <= c; k += 4) {
            int s0 = __ldg(csr + beg + k);
            int s1 = __ldg(csr + beg + k + 1);
            int s2 = __ldg(csr + beg + k + 2);
            int s3 = __ldg(csr + beg + k + 3);
            uint2 v0 = __ldg((const uint2*)(hin + (size_t)s0 * 64) + lane);
            uint2 v1 = __ldg((const uint2*)(hin + (size_t)s1 * 64) + lane);
            uint2 v2 = __ldg((const uint2*)(hin + (size_t)s2 * 64) + lane);
            uint2 v3 = __ldg((const uint2*)(hin + (size_t)s3 * 64) + lane);
            addv(a, v0); addv(a, v1); addv(a, v2); addv(a, v3);
        }
        for (; k < c; k++) {
            uint2 v = __ldg((const uint2*)(hin + (size_t)__ldg(csr + beg + k) * 64) + lane);
            addv(a, v);
        }
        addv(a, vs);

        float dd = __ldg(dinv + d);
        float t0 = fmaxf(a.x * dd + bb.x, 0.f);
        float t1 = fmaxf(a.y * dd + bb.y, 0.f);
        float t2 = fmaxf(a.z * dd + bb.z, 0.f);
        float t3 = fmaxf(a.w * dd + bb.w, 0.f);
        float o0 = t0 * sc0 + sh0, o1 = t1 * sc1 + sh1;
        float o2 = t2 * sc2 + sh2, o3 = t3 * sc3 + sh3;
        float a0 = o0 * w00 + o1 * w10 + o2 * w20 + o3 * w30;
        float a1 = o0 * w01 + o1 * w11 + o2 * w21 + o3 * w31;
        #pragma unroll
        for (int o = 16; o > 0; o >>= 1) {
            a0 += __shfl_xor_sync(0xFFFFFFFFu, a0, o);
            a1 += __shfl_xor_sync(0xFFFFFFFFu, a1, o);
        }
        if (lane == 0) {
            out[(size_t)d * 2]     = a0 + bc0;
            out[(size_t)d * 2 + 1] = a1 + bc1;
        }
    }
}

// ---------------- launcher ----------------
extern "C" void kernel_launch(void* const* d_in, const int* in_sizes, int n_in,
                              void* d_out, int out_size) {
    const float* x   = (const float*)d_in[0];
    const int*   ei  = (const int*)  d_in[1];
    const float* W1  = (const float*)d_in[2];
    const float* b1  = (const float*)d_in[3];
    const float* W2  = (const float*)d_in[4];
    const float* b2  = (const float*)d_in[5];
    const float* W3  = (const float*)d_in[6];
    const float* b3  = (const float*)d_in[7];
    const float* g1  = (const float*)d_in[8];
    const float* be1 = (const float*)d_in[9];
    const float* rm1 = (const float*)d_in[10];
    const float* rv1 = (const float*)d_in[11];
    const float* g2  = (const float*)d_in[12];
    const float* be2 = (const float*)d_in[13];
    const float* rm2 = (const float*)d_in[14];
    const float* rv2 = (const float*)d_in[15];
    const float* g3  = (const float*)d_in[16];
    const float* be3 = (const float*)d_in[17];
    const float* rm3 = (const float*)d_in[18];
    const float* rv3 = (const float*)d_in[19];
    const float* Wc  = (const float*)d_in[20];
    const float* bc  = (const float*)d_in[21];
    float* out = (float*)d_out;

    int n = in_sizes[0] / HD;
    int e = in_sizes[1] / 2;
    const int* src = ei;
    const int* dst = ei + e;

    float *pdinv;
    uint32_t *ph, *py;
    int *pcnt, *prow, *pcur, *pcsr, *pbsum;
    uint32_t *pwhi1, *pwlo1, *pwhi2, *pwlo2, *pwhi3, *pwlo3;
    cudaGetSymbolAddress((void**)&ph,    g_h);
    cudaGetSymbolAddress((void**)&py,    g_y);
    cudaGetSymbolAddress((void**)&pdinv, g_dinv);
    cudaGetSymbolAddress((void**)&pcnt,  g_cnt);
    cudaGetSymbolAddress((void**)&prow,  g_rowptr);
    cudaGetSymbolAddress((void**)&pcur,  g_cursor);
    cudaGetSymbolAddress((void**)&pcsr,  g_csr);
    cudaGetSymbolAddress((void**)&pbsum, g_bsum);
    cudaGetSymbolAddress((void**)&pwhi1, g_whi1);
    cudaGetSymbolAddress((void**)&pwlo1, g_wlo1);
    cudaGetSymbolAddress((void**)&pwhi2, g_whi2);
    cudaGetSymbolAddress((void**)&pwlo2, g_wlo2);
    cudaGetSymbolAddress((void**)&pwhi3, g_whi3);
    cudaGetSymbolAddress((void**)&pwlo3, g_wlo3);

    cudaFuncSetAttribute(k_gemm_f32a, cudaFuncAttributeMaxDynamicSharedMemorySize, GEMM_SMEM);
    cudaFuncSetAttribute(k_gemm_h16a, cudaFuncAttributeMaxDynamicSharedMemorySize, GEMM_SMEM);

    const int T = 256;
    int bn_n  = (n + T - 1) / T;
    int bn_e  = (e + T - 1) / T;
    int bn_gm = (n + 127) / 128;
    int nb_sc = (n + 511) / 512;
    int bn_ag = 4096;

    // init + degree (GEMM1 at 4th launch = profiled slot)
    k_init  <<<bn_n, T>>>(W1, pwhi1, pwlo1, pcnt, n);
    k_count <<<bn_e, T>>>(dst, pcnt, e);
    k_dinv  <<<bn_n, T>>>(pcnt, pdinv, n);
    k_gemm_f32a<<<bn_gm, T, GEMM_SMEM>>>(x, pwhi1, pwlo1, pdinv, ph, n);

    // CSR build + W2/W3 splits
    k_wsplit2   <<<32, T>>>(W2, pwhi2, pwlo2, W3, pwhi3, pwlo3);
    k_scan_block<<<nb_sc, 512>>>(pcnt, prow, pbsum, n);
    k_scan_sums <<<1, 256>>>(pbsum, nb_sc);
    k_scan_add  <<<nb_sc, 512>>>(prow, pcur, pbsum, n);
    k_fill      <<<bn_e, T>>>(src, dst, pcur, pcsr, e);

    // layer 1 aggregate -> layer 2
    k_aggregate<<<bn_ag, T>>>(ph, prow, pcnt, pdinv, b1, g1, be1, rm1, rv1, pcsr, py, n);
    k_gemm_h16a<<<bn_gm, T, GEMM_SMEM>>>(py, pwhi2, pwlo2, pdinv, ph, n);
    // layer 2 aggregate -> layer 3
    k_aggregate<<<bn_ag, T>>>(ph, prow, pcnt, pdinv, b2, g2, be2, rm2, rv2, pcsr, py, n);
    k_gemm_h16a<<<bn_gm, T, GEMM_SMEM>>>(py, pwhi3, pwlo3, pdinv, ph, n);
    // layer 3 aggregate fused with classifier
    k_agg_cls  <<<bn_ag, T>>>(ph, prow, pcnt, pdinv, pcsr,
                              b3, g3, be3, rm3, rv3, Wc, bc, out, n);
}

// round 16
// speedup vs baseline: 1.0910x; 1.0068x over previous
#include <cuda_runtime.h>
#include <cuda_fp16.h>
#include <cstdint>
#include <cstddef>

#define MAXN 100000
#define MAXE 1600000
#define HD   128

// ---------------- static device scratch ----------------
__device__ uint32_t g_h  [(size_t)MAXN * 64];   // GEMM out, packed fp16x2 (gathered)
__device__ uint32_t g_y  [(size_t)MAXN * 64];   // aggregate out, packed fp16x2
__device__ float    g_dinv[MAXN];
__device__ int      g_cnt [MAXN];
__device__ int      g_rowptr[MAXN];
__device__ int      g_cursor[MAXN];
__device__ int      g_csr [MAXE];
__device__ int      g_bsum[256];
__device__ uint32_t g_whi1[8192], g_wlo1[8192];
__device__ uint32_t g_whi2[8192], g_wlo2[8192];
__device__ uint32_t g_whi3[8192], g_wlo3[8192];

// ---------------- helpers ----------------
__device__ __forceinline__ void hsplit(float f, __half& h, __half& l) {
    h = __float2half_rn(f);
    l = __float2half_rn(f - __half2float(h));
}
__device__ __forceinline__ uint32_t hpack(__half a, __half b) {
    return ((uint32_t)__half_as_ushort(b) << 16) | (uint32_t)__half_as_ushort(a);
}
__device__ __forceinline__ void mma16816(float* d, const uint32_t* a, const uint32_t* b) {
    asm volatile("mma.sync.aligned.m16n8k16.row.col.f32.f16.f16.f32 "
        "{%0,%1,%2,%3}, {%4,%5,%6,%7}, {%8,%9}, {%0,%1,%2,%3};"
        : "+f"(d[0]), "+f"(d[1]), "+f"(d[2]), "+f"(d[3])
        : "r"(a[0]), "r"(a[1]), "r"(a[2]), "r"(a[3]), "r"(b[0]), "r"(b[1]));
}
__device__ __forceinline__ void wsplit_one(const float* __restrict__ W,
                                           uint32_t* whi, uint32_t* wlo, int i) {
    int nn = i >> 6;
    int k2 = i & 63;
    float f0 = __ldg(W + (size_t)(2 * k2)     * 128 + nn);
    float f1 = __ldg(W + (size_t)(2 * k2 + 1) * 128 + nn);
    __half h0, l0, h1, l1;
    hsplit(f0, h0, l0);
    hsplit(f1, h1, l1);
    whi[i] = hpack(h0, h1);
    wlo[i] = hpack(l0, l1);
}
__device__ __forceinline__ void addv(float4& a, uint2 v) {
    float2 p0 = __half22float2(*(__half2*)&v.x);
    float2 p1 = __half22float2(*(__half2*)&v.y);
    a.x += p0.x; a.y += p0.y; a.z += p1.x; a.w += p1.y;
}

// ---------------- init / CSR build ----------------
__global__ void k_init(const float* __restrict__ W1, uint32_t* whi, uint32_t* wlo,
                       int* cnt, int n) {
    int i = blockIdx.x * blockDim.x + threadIdx.x;
    if (i < n) cnt[i] = 0;
    if (i < 8192) wsplit_one(W1, whi, wlo, i);
}
__global__ void k_count(const int* __restrict__ dst, int* cnt, int e) {
    int i = blockIdx.x * blockDim.x + threadIdx.x;
    if (i < e) atomicAdd(&cnt[dst[i]], 1);
}
__global__ void k_dinv(const int* __restrict__ cnt, float* dinv, int n) {
    int i = blockIdx.x * blockDim.x + threadIdx.x;
    if (i < n) dinv[i] = rsqrtf((float)(cnt[i] + 1));
}
__global__ void k_wsplit2(const float* __restrict__ W2, uint32_t* whi2, uint32_t* wlo2,
                          const float* __restrict__ W3, uint32_t* whi3, uint32_t* wlo3) {
    int i = blockIdx.x * blockDim.x + threadIdx.x;
    if (i < 8192) {
        wsplit_one(W2, whi2, wlo2, i);
        wsplit_one(W3, whi3, wlo3, i);
    }
}
__global__ void k_scan_block(const int* __restrict__ in, int* out, int* bsum, int n) {
    __shared__ int s[512];
    int i = blockIdx.x * 512 + threadIdx.x;
    int v = (i < n) ? in[i] : 0;
    s[threadIdx.x] = v;
    __syncthreads();
    #pragma unroll
    for (int o = 1; o < 512; o <<= 1) {
        int t = (threadIdx.x >= o) ? s[threadIdx.x - o] : 0;
        __syncthreads();
        s[threadIdx.x] += t;
        __syncthreads();
    }
    if (i < n) out[i] = s[threadIdx.x] - v;
    if (threadIdx.x == 511) bsum[blockIdx.x] = s[511];
}
__global__ void k_scan_sums(int* bsum, int nb) {
    __shared__ int s[256];
    int v = (threadIdx.x < nb) ? bsum[threadIdx.x] : 0;
    s[threadIdx.x] = v;
    __syncthreads();
    #pragma unroll
    for (int o = 1; o < 256; o <<= 1) {
        int t = (threadIdx.x >= o) ? s[threadIdx.x - o] : 0;
        __syncthreads();
        s[threadIdx.x] += t;
        __syncthreads();
    }
    if (threadIdx.x < nb) bsum[threadIdx.x] = s[threadIdx.x] - v;
}
__global__ void k_scan_add(int* out, int* cursor, const int* __restrict__ bsum, int n) {
    int i = blockIdx.x * 512 + threadIdx.x;
    if (i < n) {
        int v = out[i] + bsum[blockIdx.x];
        out[i] = v;
        cursor[i] = v;
    }
}
__global__ void k_fill(const int* __restrict__ src, const int* __restrict__ dst,
                       int* cursor, int* csr, int e) {
    int i = blockIdx.x * blockDim.x + threadIdx.x;
    if (i < e) {
        int p = atomicAdd(&cursor[dst[i]], 1);
        csr[p] = src[i];
    }
}

// ---------------- GEMM core: 128-row tile, single-sync (all LDG up front) ----------
#define AROW   68
#define ABUF   (128 * AROW)            // 8704 u32 (full K)
#define BROW   36
#define BBUF   (128 * BROW)            // 4608 u32 (one chunk, one of hi/lo)
#define GEMM_SMEM ((ABUF + 4 * BBUF) * 4)   // 108544

struct GemmCore {
    template <typename AFill>
    static __device__ __forceinline__
    void run(AFill afill, const uint32_t* __restrict__ Bhi, const uint32_t* __restrict__ Blo,
             const float* __restrict__ dinv, uint32_t* __restrict__ C, int n,
             uint32_t* sm) {
        uint32_t* As = sm;
        uint32_t* Bs = sm + ABUF;

        const int tid  = threadIdx.x;
        const int wid  = tid >> 5;
        const int lane = tid & 31;
        const int qg   = lane >> 2;
        const int qt   = lane & 3;
        const int wm   = wid & 3;
        const int wn   = wid >> 2;
        const int r0   = blockIdx.x * 128;

        afill(As, r0, tid, n);
        #pragma unroll
        for (int ch = 0; ch < 2; ch++) {
            uint32_t* bh = Bs + (ch * 2)     * BBUF;
            uint32_t* bl = Bs + (ch * 2 + 1) * BBUF;
            #pragma unroll
            for (int it = 0; it < 16; it++) {
                int i  = tid + it * 256;
                int nn = i >> 5;
                int k2 = i & 31;
                bh[nn * BROW + k2] = __ldg(Bhi + nn * 64 + ch * 32 + k2);
                bl[nn * BROW + k2] = __ldg(Blo + nn * 64 + ch * 32 + k2);
            }
        }
        __syncthreads();

        float acc[2][8][4];
        #pragma unroll
        for (int a = 0; a < 2; a++)
            #pragma unroll
            for (int b = 0; b < 8; b++)
                #pragma unroll
                for (int c = 0; c < 4; c++) acc[a][b][c] = 0.f;

        #pragma unroll
        for (int ch = 0; ch < 2; ch++) {
            uint32_t* bhp = Bs + (ch * 2)     * BBUF;
            uint32_t* blp = Bs + (ch * 2 + 1) * BBUF;
            #pragma unroll
            for (int ks = 0; ks < 4; ks++) {
                uint32_t ah[2][4];
                #pragma unroll
                for (int mt = 0; mt < 2; mt++) {
                    int rb = wm * 32 + mt * 16;
                    int p0 = (rb + qg)     * AROW + ch * 32 + ks * 8 + qt;
                    int p8 = (rb + qg + 8) * AROW + ch * 32 + ks * 8 + qt;
                    ah[mt][0] = As[p0]; ah[mt][1] = As[p8];
                    ah[mt][2] = As[p0 + 4]; ah[mt][3] = As[p8 + 4];
                }
                #pragma unroll
                for (int nt = 0; nt < 8; nt++) {
                    int nb = (wn * 64 + nt * 8 + qg) * BROW + ks * 8 + qt;
                    uint32_t bh[2] = {bhp[nb], bhp[nb + 4]};
                    uint32_t bl[2] = {blp[nb], blp[nb + 4]};
                    #pragma unroll
                    for (int mt = 0; mt < 2; mt++) {
                        mma16816(acc[mt][nt], ah[mt], bh);
                        mma16816(acc[mt][nt], ah[mt], bl);
                    }
                }
            }
        }

        #pragma unroll
        for (int mt = 0; mt < 2; mt++) {
            int row0 = r0 + wm * 32 + mt * 16 + qg;
            int row1 = row0 + 8;
            float dv0 = (row0 < n) ? __ldg(dinv + row0) : 0.f;
            float dv1 = (row1 < n) ? __ldg(dinv + row1) : 0.f;
            #pragma unroll
            for (int nt = 0; nt < 8; nt++) {
                int c2 = wn * 32 + nt * 4 + qt;
                if (row0 < n)
                    C[(size_t)row0 * 64 + c2] = hpack(__float2half_rn(acc[mt][nt][0] * dv0),
                                                      __float2half_rn(acc[mt][nt][1] * dv0));
                if (row1 < n)
                    C[(size_t)row1 * 64 + c2] = hpack(__float2half_rn(acc[mt][nt][2] * dv1),
                                                      __float2half_rn(acc[mt][nt][3] * dv1));
            }
        }
    }
};

__global__ void __launch_bounds__(256, 2)
k_gemm_f32a(const float* __restrict__ A, const uint32_t* __restrict__ Bhi,
            const uint32_t* __restrict__ Blo, const float* __restrict__ dinv,
            uint32_t* __restrict__ C, int n) {
    extern __shared__ uint32_t sm[];
    auto afill = [A](uint32_t* As, int r0, int tid, int n) {
        #pragma unroll
        for (int it = 0; it < 16; it++) {
            int i   = tid + it * 256;
            int row = i >> 5;
            int q   = i & 31;
            int gr  = r0 + row;
            float4 v = make_float4(0.f, 0.f, 0.f, 0.f);
            if (gr < n) v = *(const float4*)(A + (size_t)gr * 128 + q * 4);
            int p = row * AROW + q * 2;
            As[p]     = hpack(__float2half_rn(v.x), __float2half_rn(v.y));
            As[p + 1] = hpack(__float2half_rn(v.z), __float2half_rn(v.w));
        }
    };
    GemmCore::run(afill, Bhi, Blo, dinv, C, n, sm);
}

__global__ void __launch_bounds__(256, 2)
k_gemm_h16a(const uint32_t* __restrict__ A, const uint32_t* __restrict__ Bhi,
            const uint32_t* __restrict__ Blo, const float* __restrict__ dinv,
            uint32_t* __restrict__ C, int n) {
    extern __shared__ uint32_t sm[];
    auto afill = [A](uint32_t* As, int r0, int tid, int n) {
        #pragma unroll
        for (int it = 0; it < 16; it++) {
            int i   = tid + it * 256;
            int row = i >> 5;
            int k4  = (i & 31) * 2;
            int gr  = r0 + row;
            uint2 v = make_uint2(0u, 0u);
            if (gr < n) v = *(const uint2*)(A + (size_t)gr * 64 + k4);
            *(uint2*)(As + row * AROW + k4) = v;
        }
    };
    GemmCore::run(afill, Bhi, Blo, dinv, C, n, sm);
}

// ---------------- aggregate (fp16 gather) + bias/relu/BN -> y packed fp16 ----------------
__global__ void k_aggregate(const uint32_t* __restrict__ hs,
                            const int* __restrict__ rowptr, const int* __restrict__ cnt,
                            const float* __restrict__ dinv,
                            const float* __restrict__ b,  const float* __restrict__ g,
                            const float* __restrict__ be, const float* __restrict__ rm,
                            const float* __restrict__ rv, const int* __restrict__ csr,
                            uint32_t* __restrict__ y, int n) {
    int warp = (blockIdx.x * blockDim.x + threadIdx.x) >> 5;
    int lane = threadIdx.x & 31;
    int nw   = (gridDim.x * blockDim.x) >> 5;
    int j    = lane * 4;

    float4 bb = __ldg((const float4*)(b  + j));
    float4 gg = __ldg((const float4*)(g  + j));
    float4 rr = __ldg((const float4*)(rv + j));
    float4 mm = __ldg((const float4*)(rm + j));
    float4 ee = __ldg((const float4*)(be + j));
    float sc0 = gg.x * rsqrtf(rr.x + 1e-5f), sh0 = ee.x - mm.x * sc0;
    float sc1 = gg.y * rsqrtf(rr.y + 1e-5f), sh1 = ee.y - mm.y * sc1;
    float sc2 = gg.z * rsqrtf(rr.z + 1e-5f), sh2 = ee.z - mm.z * sc2;
    float sc3 = gg.w * rsqrtf(rr.w + 1e-5f), sh3 = ee.w - mm.w * sc3;

    for (int d = warp; d < n; d += nw) {
        float4 a = make_float4(0.f, 0.f, 0.f, 0.f);
        uint2 vs = __ldg((const uint2*)(hs + (size_t)d * 64) + lane);
        int beg = __ldg(rowptr + d);
        int c   = __ldg(cnt + d);
        int k = 0;
        for (; k + 4 <= c; k += 4) {
            int s0 = __ldg(csr + beg + k);
            int s1 = __ldg(csr + beg + k + 1);
            int s2 = __ldg(csr + beg + k + 2);
            int s3 = __ldg(csr + beg + k + 3);
            uint2 v0 = __ldg((const uint2*)(hs + (size_t)s0 * 64) + lane);
            uint2 v1 = __ldg((const uint2*)(hs + (size_t)s1 * 64) + lane);
            uint2 v2 = __ldg((const uint2*)(hs + (size_t)s2 * 64) + lane);
            uint2 v3 = __ldg((const uint2*)(hs + (size_t)s3 * 64) + lane);
            addv(a, v0); addv(a, v1); addv(a, v2); addv(a, v3);
        }
        for (; k < c; k++) {
            uint2 v = __ldg((const uint2*)(hs + (size_t)__ldg(csr + beg + k) * 64) + lane);
            addv(a, v);
        }
        addv(a, vs);

        float w = __ldg(dinv + d);
        float t0 = fmaxf(a.x * w + bb.x, 0.f);
        float t1 = fmaxf(a.y * w + bb.y, 0.f);
        float t2 = fmaxf(a.z * w + bb.z, 0.f);
        float t3 = fmaxf(a.w * w + bb.w, 0.f);
        uint2 o;
        o.x = hpack(__float2half_rn(t0 * sc0 + sh0), __float2half_rn(t1 * sc1 + sh1));
        o.y = hpack(__float2half_rn(t2 * sc2 + sh2), __float2half_rn(t3 * sc3 + sh3));
        *((uint2*)(y + (size_t)d * 64) + lane) = o;
    }
}

// ---------------- fused aggregate -> classifier (layer 3) ----------------
__global__ void k_agg_cls(const uint32_t* __restrict__ hin,
                          const int* __restrict__ rowptr, const int* __restrict__ cnt,
                          const float* __restrict__ dinv, const int* __restrict__ csr,
                          const float* __restrict__ bias, const float* __restrict__ gam,
                          const float* __restrict__ bet, const float* __restrict__ rmean,
                          const float* __restrict__ rvar,
                          const float* __restrict__ Wc, const float* __restrict__ bc,
                          float* __restrict__ out, int n) {
    int warp = (blockIdx.x * blockDim.x + threadIdx.x) >> 5;
    int lane = threadIdx.x & 31;
    int nw   = (gridDim.x * blockDim.x) >> 5;
    int j    = lane * 4;

    float4 bb = __ldg((const float4*)(bias  + j));
    float4 gg = __ldg((const float4*)(gam   + j));
    float4 rr = __ldg((const float4*)(rvar  + j));
    float4 mm = __ldg((const float4*)(rmean + j));
    float4 ee = __ldg((const float4*)(bet   + j));
    float sc0 = gg.x * rsqrtf(rr.x + 1e-5f), sh0 = ee.x - mm.x * sc0;
    float sc1 = gg.y * rsqrtf(rr.y + 1e-5f), sh1 = ee.y - mm.y * sc1;
    float sc2 = gg.z * rsqrtf(rr.z + 1e-5f), sh2 = ee.z - mm.z * sc2;
    float sc3 = gg.w * rsqrtf(rr.w + 1e-5f), sh3 = ee.w - mm.w * sc3;
    float w00 = __ldg(Wc + (j + 0) * 2), w01 = __ldg(Wc + (j + 0) * 2 + 1);
    float w10 = __ldg(Wc + (j + 1) * 2), w11 = __ldg(Wc + (j + 1) * 2 + 1);
    float w20 = __ldg(Wc + (j + 2) * 2), w21 = __ldg(Wc + (j + 2) * 2 + 1);
    float w30 = __ldg(Wc + (j + 3) * 2), w31 = __ldg(Wc + (j + 3) * 2 + 1);
    float bc0 = __ldg(bc), bc1 = __ldg(bc + 1);

    for (int d = warp; d < n; d += nw) {
        float4 a = make_float4(0.f, 0.f, 0.f, 0.f);
        uint2 vs = __ldg((const uint2*)(hin + (size_t)d * 64) + lane);
        int beg = __ldg(rowptr + d);
        int c   = __ldg(cnt + d);
        int k = 0;
        for (; k + 4 <= c; k += 4) {
            int s0 = __ldg(csr + beg + k);
            int s1 = __ldg(csr + beg + k + 1);
            int s2 = __ldg(csr + beg + k + 2);
            int s3 = __ldg(csr + beg + k + 3);
            uint2 v0 = __ldg((const uint2*)(hin + (size_t)s0 * 64) + lane);
            uint2 v1 = __ldg((const uint2*)(hin + (size_t)s1 * 64) + lane);
            uint2 v2 = __ldg((const uint2*)(hin + (size_t)s2 * 64) + lane);
            uint2 v3 = __ldg((const uint2*)(hin + (size_t)s3 * 64) + lane);
            addv(a, v0); addv(a, v1); addv(a, v2); addv(a, v3);
        }
        for (; k < c; k++) {
            uint2 v = __ldg((const uint2*)(hin + (size_t)__ldg(csr + beg + k) * 64) + lane);
            addv(a, v);
        }
        addv(a, vs);

        float dd = __ldg(dinv + d);
        float t0 = fmaxf(a.x * dd + bb.x, 0.f);
        float t1 = fmaxf(a.y * dd + bb.y, 0.f);
        float t2 = fmaxf(a.z * dd + bb.z, 0.f);
        float t3 = fmaxf(a.w * dd + bb.w, 0.f);
        float o0 = t0 * sc0 + sh0, o1 = t1 * sc1 + sh1;
        float o2 = t2 * sc2 + sh2, o3 = t3 * sc3 + sh3;
        float a0 = o0 * w00 + o1 * w10 + o2 * w20 + o3 * w30;
        float a1 = o0 * w01 + o1 * w11 + o2 * w21 + o3 * w31;
        #pragma unroll
        for (int o = 16; o > 0; o >>= 1) {
            a0 += __shfl_xor_sync(0xFFFFFFFFu, a0, o);
            a1 += __shfl_xor_sync(0xFFFFFFFFu, a1, o);
        }
        if (lane == 0) {
            out[(size_t)d * 2]     = a0 + bc0;
            out[(size_t)d * 2 + 1] = a1 + bc1;
        }
    }
}

// ---------------- launcher (fork/join overlap of CSR chain with GEMM1) ----------------
extern "C" void kernel_launch(void* const* d_in, const int* in_sizes, int n_in,
                              void* d_out, int out_size) {
    const float* x   = (const float*)d_in[0];
    const int*   ei  = (const int*)  d_in[1];
    const float* W1  = (const float*)d_in[2];
    const float* b1  = (const float*)d_in[3];
    const float* W2  = (const float*)d_in[4];
    const float* b2  = (const float*)d_in[5];
    const float* W3  = (const float*)d_in[6];
    const float* b3  = (const float*)d_in[7];
    const float* g1  = (const float*)d_in[8];
    const float* be1 = (const float*)d_in[9];
    const float* rm1 = (const float*)d_in[10];
    const float* rv1 = (const float*)d_in[11];
    const float* g2  = (const float*)d_in[12];
    const float* be2 = (const float*)d_in[13];
    const float* rm2 = (const float*)d_in[14];
    const float* rv2 = (const float*)d_in[15];
    const float* g3  = (const float*)d_in[16];
    const float* be3 = (const float*)d_in[17];
    const float* rm3 = (const float*)d_in[18];
    const float* rv3 = (const float*)d_in[19];
    const float* Wc  = (const float*)d_in[20];
    const float* bc  = (const float*)d_in[21];
    float* out = (float*)d_out;

    int n = in_sizes[0] / HD;
    int e = in_sizes[1] / 2;
    const int* src = ei;
    const int* dst = ei + e;

    float *pdinv;
    uint32_t *ph, *py;
    int *pcnt, *prow, *pcur, *pcsr, *pbsum;
    uint32_t *pwhi1, *pwlo1, *pwhi2, *pwlo2, *pwhi3, *pwlo3;
    cudaGetSymbolAddress((void**)&ph,    g_h);
    cudaGetSymbolAddress((void**)&py,    g_y);
    cudaGetSymbolAddress((void**)&pdinv, g_dinv);
    cudaGetSymbolAddress((void**)&pcnt,  g_cnt);
    cudaGetSymbolAddress((void**)&prow,  g_rowptr);
    cudaGetSymbolAddress((void**)&pcur,  g_cursor);
    cudaGetSymbolAddress((void**)&pcsr,  g_csr);
    cudaGetSymbolAddress((void**)&pbsum, g_bsum);
    cudaGetSymbolAddress((void**)&pwhi1, g_whi1);
    cudaGetSymbolAddress((void**)&pwlo1, g_wlo1);
    cudaGetSymbolAddress((void**)&pwhi2, g_whi2);
    cudaGetSymbolAddress((void**)&pwlo2, g_wlo2);
    cudaGetSymbolAddress((void**)&pwhi3, g_whi3);
    cudaGetSymbolAddress((void**)&pwlo3, g_wlo3);

    cudaFuncSetAttribute(k_gemm_f32a, cudaFuncAttributeMaxDynamicSharedMemorySize, GEMM_SMEM);
    cudaFuncSetAttribute(k_gemm_h16a, cudaFuncAttributeMaxDynamicSharedMemorySize, GEMM_SMEM);

    // one-time stream/event creation (no device memory; identical work every call)
    static cudaStream_t s_side = nullptr;
    static cudaEvent_t  s_ev_fork = nullptr, s_ev_join = nullptr;
    if (s_side == nullptr) {
        cudaStreamCreateWithFlags(&s_side, cudaStreamNonBlocking);
        cudaEventCreateWithFlags(&s_ev_fork, cudaEventDisableTiming);
        cudaEventCreateWithFlags(&s_ev_join, cudaEventDisableTiming);
    }

    const int T = 256;
    int bn_n  = (n + T - 1) / T;
    int bn_e  = (e + T - 1) / T;
    int bn_gm = (n + 127) / 128;
    int nb_sc = (n + 511) / 512;
    int bn_ag = 4096;

    // main stream: init -> count
    k_init  <<<bn_n, T>>>(W1, pwhi1, pwlo1, pcnt, n);
    k_count <<<bn_e, T>>>(dst, pcnt, e);

    // fork: CSR chain + W2/W3 splits on side stream (depends only on cnt)
    cudaEventRecord(s_ev_fork, 0);
    cudaStreamWaitEvent(s_side, s_ev_fork, 0);
    k_scan_block<<<nb_sc, 512, 0, s_side>>>(pcnt, prow, pbsum, n);
    k_scan_sums <<<1, 256, 0, s_side>>>(pbsum, nb_sc);
    k_scan_add  <<<nb_sc, 512, 0, s_side>>>(prow, pcur, pbsum, n);
    k_fill      <<<bn_e, T, 0, s_side>>>(src, dst, pcur, pcsr, e);
    k_wsplit2   <<<32, T, 0, s_side>>>(W2, pwhi2, pwlo2, W3, pwhi3, pwlo3);
    cudaEventRecord(s_ev_join, s_side);

    // main stream: dinv + GEMM1 (co-runs with side chain)
    k_dinv      <<<bn_n, T>>>(pcnt, pdinv, n);
    k_gemm_f32a <<<bn_gm, T, GEMM_SMEM>>>(x, pwhi1, pwlo1, pdinv, ph, n);

    // join before first aggregate (needs rowptr/csr) and GEMM2 (needs whi2)
    cudaStreamWaitEvent(0, s_ev_join, 0);

    // layer 1 aggregate -> layer 2
    k_aggregate<<<bn_ag, T>>>(ph, prow, pcnt, pdinv, b1, g1, be1, rm1, rv1, pcsr, py, n);
    k_gemm_h16a<<<bn_gm, T, GEMM_SMEM>>>(py, pwhi2, pwlo2, pdinv, ph, n);
    // layer 2 aggregate -> layer 3
    k_aggregate<<<bn_ag, T>>>(ph, prow, pcnt, pdinv, b2, g2, be2, rm2, rv2, pcsr, py, n);
    k_gemm_h16a<<<bn_gm, T, GEMM_SMEM>>>(py, pwhi3, pwlo3, pdinv, ph, n);
    // layer 3 aggregate fused with classifier
    k_agg_cls  <<<bn_ag, T>>>(ph, prow, pcnt, pdinv, pcsr,
                              b3, g3, be3, rm3, rv3, Wc, bc, out, n);
}